// round 4
// baseline (speedup 1.0000x reference)
#include <cuda_runtime.h>
#include <cuda_bf16.h>

// B=8, SEQ=4096, DIM=64.
// out = scale * rope(Q) @ (rope(K)^T @ rope(V))   (associativity; no softmax)
// scale = 1/sqrt(64) = 0.125
// Inputs: q,k,v (8,4096,64) fp32 ; freq_q/k/v (4096,32,2) fp32. Output fp32.

#define BATCH   8
#define SEQ     4096
#define DIM     64
#define NCHUNK  128
#define CHUNK   (SEQ / NCHUNK)   // 32 rows per k1 block

__device__ float g_partials[NCHUNK * BATCH * DIM * DIM];  // 16 MB (L2-resident)
__device__ float g_M[BATCH * DIM * DIM];                  // 128 KB

typedef unsigned long long ull;

__device__ __forceinline__ void fma2(ull& d, ull a, ull b) {
    asm("fma.rn.f32x2 %0, %1, %2, %0;" : "+l"(d) : "l"(a), "l"(b));
}
__device__ __forceinline__ float2 up2(ull v) {
    float2 r;
    asm("mov.b64 {%0,%1}, %2;" : "=f"(r.x), "=f"(r.y) : "l"(v));
    return r;
}
__device__ __forceinline__ float4 rope4(float4 x, float4 f) {
    float4 o;
    o.x = x.x * f.x - x.y * f.y;  o.y = x.x * f.y + x.y * f.x;
    o.z = x.z * f.z - x.w * f.w;  o.w = x.z * f.w + x.w * f.z;
    return o;
}
// swizzled pair-slot: conflict-free for both staging stores and GEMM loads
#define PSLOT(rg, d) (((rg) + ((d) >> 2) + 4 * ((d) & 3)) & 15)

// ---------------------------------------------------------------------------
// Kernel 1: partial M = sum_{r in chunk} rope(k_r) ⊗ rope(v_r)
// 128 threads; thread (ti=t&15, tj=t>>4) owns rows 4ti..4ti+3 x cols 8tj..8tj+7.
// k values staged PRE-DUPLICATED: skd[ii][r][2*PSLOT(ti,r)] = {k[r][4ti+ii]}x2,
// so the inner loop is pure LDS.64 + FFMA2 (no per-iter packing MOVs).
// ---------------------------------------------------------------------------
__global__ __launch_bounds__(128) void kv_outer_kernel(
    const float* __restrict__ K, const float* __restrict__ V,
    const float* __restrict__ FK, const float* __restrict__ FV)
{
    const int b = blockIdx.y;
    const int c = blockIdx.x;
    const int t = threadIdx.x;

    __shared__ float skd[4][CHUNK][32];   // 16 KB  (dup pairs, swizzled slots)
    __shared__ float sv[CHUNK][DIM];      // 8 KB

    const float4* K4  = (const float4*)(K  + ((size_t)b * SEQ + c * CHUNK) * DIM);
    const float4* V4  = (const float4*)(V  + ((size_t)b * SEQ + c * CHUNK) * DIM);
    const float4* FK4 = (const float4*)(FK + (size_t)c * CHUNK * DIM);
    const float4* FV4 = (const float4*)(FV + (size_t)c * CHUNK * DIM);

    // stage + rope the 32x64 tile (512 float4 per tensor, 4 per thread)
#pragma unroll
    for (int u = 0; u < 4; u++) {
        const int f   = t + 128 * u;
        const int r   = f >> 4;       // row in chunk
        const int c4  = f & 15;       // float4 slot in row (i = 4*c4+cc)
        const float4 kr = rope4(K4[f], FK4[f]);
        const float4 vr = rope4(V4[f], FV4[f]);
        *(float4*)&sv[r][4 * c4] = vr;
        const int po = 2 * PSLOT(c4, r);
        *(float2*)&skd[0][r][po] = make_float2(kr.x, kr.x);
        *(float2*)&skd[1][r][po] = make_float2(kr.y, kr.y);
        *(float2*)&skd[2][r][po] = make_float2(kr.z, kr.z);
        *(float2*)&skd[3][r][po] = make_float2(kr.w, kr.w);
    }
    __syncthreads();

    const int ti = t & 15;
    const int tj = t >> 4;
    const int j0 = 8 * tj;

    ull acc[4][4];
#pragma unroll
    for (int i = 0; i < 4; i++)
#pragma unroll
        for (int u = 0; u < 4; u++) acc[i][u] = 0ULL;

#pragma unroll 16
    for (int r = 0; r < CHUNK; r++) {
        const int po = 2 * PSLOT(ti, r);
        const ull k0 = *(const ull*)&skd[0][r][po];
        const ull k1 = *(const ull*)&skd[1][r][po];
        const ull k2 = *(const ull*)&skd[2][r][po];
        const ull k3 = *(const ull*)&skd[3][r][po];
        const ull* vr = (const ull*)&sv[r][j0];
        const ull v0 = vr[0], v1 = vr[1], v2 = vr[2], v3 = vr[3];
        fma2(acc[0][0], k0, v0); fma2(acc[0][1], k0, v1);
        fma2(acc[0][2], k0, v2); fma2(acc[0][3], k0, v3);
        fma2(acc[1][0], k1, v0); fma2(acc[1][1], k1, v1);
        fma2(acc[1][2], k1, v2); fma2(acc[1][3], k1, v3);
        fma2(acc[2][0], k2, v0); fma2(acc[2][1], k2, v1);
        fma2(acc[2][2], k2, v2); fma2(acc[2][3], k2, v3);
        fma2(acc[3][0], k3, v0); fma2(acc[3][1], k3, v1);
        fma2(acc[3][2], k3, v2); fma2(acc[3][3], k3, v3);
    }

    float* P = &g_partials[((size_t)c * BATCH + b) * (DIM * DIM)];
    const int i0 = 4 * ti;
#pragma unroll
    for (int i = 0; i < 4; i++) {
#pragma unroll
        for (int w = 0; w < 2; w++) {
            const float2 a  = up2(acc[i][2 * w]);
            const float2 b2 = up2(acc[i][2 * w + 1]);
            *(float4*)&P[(i0 + i) * DIM + j0 + 4 * w] =
                make_float4(a.x, a.y, b2.x, b2.y);
        }
    }
}

// ---------------------------------------------------------------------------
// Kernel 2: reduce NCHUNK partials -> g_M  (8192 float4 outputs)
// ---------------------------------------------------------------------------
__global__ __launch_bounds__(256) void reduce_kernel()
{
    const int idx = blockIdx.x * 256 + threadIdx.x;   // float4 index
    const float4* P = (const float4*)g_partials;
    float4 s0 = make_float4(0.f, 0.f, 0.f, 0.f);
    float4 s1 = make_float4(0.f, 0.f, 0.f, 0.f);
    float4 s2 = make_float4(0.f, 0.f, 0.f, 0.f);
    float4 s3 = make_float4(0.f, 0.f, 0.f, 0.f);
#pragma unroll 4
    for (int c = 0; c < NCHUNK; c += 4) {
        const float4 a = P[(size_t)(c + 0) * 8192 + idx];
        const float4 b = P[(size_t)(c + 1) * 8192 + idx];
        const float4 d = P[(size_t)(c + 2) * 8192 + idx];
        const float4 e = P[(size_t)(c + 3) * 8192 + idx];
        s0.x += a.x; s0.y += a.y; s0.z += a.z; s0.w += a.w;
        s1.x += b.x; s1.y += b.y; s1.z += b.z; s1.w += b.w;
        s2.x += d.x; s2.y += d.y; s2.z += d.z; s2.w += d.w;
        s3.x += e.x; s3.y += e.y; s3.z += e.z; s3.w += e.w;
    }
    ((float4*)g_M)[idx] = make_float4(s0.x + s1.x + s2.x + s3.x,
                                      s0.y + s1.y + s2.y + s3.y,
                                      s0.z + s1.z + s2.z + s3.z,
                                      s0.w + s1.w + s2.w + s3.w);
}

// ---------------------------------------------------------------------------
// Kernel 3: out[b,row,:] = scale * rope(Q[b,row,:]) @ M[b]
// Identical structure to k1: q is the dup-staged operand (reduction index d),
// M rows are the broadcast pairs. 64 q-rows x 64 cols per CTA, 128 threads.
// ---------------------------------------------------------------------------
__global__ __launch_bounds__(128) void qm_kernel(
    const float* __restrict__ Q, const float* __restrict__ FQ,
    float* __restrict__ OUT)
{
    const int b = blockIdx.y;
    const int rc = blockIdx.x;   // 64-row chunk
    const int t = threadIdx.x;

    __shared__ float sqd[4][DIM][32];   // 32 KB: sqd[row&3][d][2*PSLOT(row>>2,d)]
    __shared__ float sM[DIM * DIM];     // 16 KB

    // load M[b]
    {
        const float4* Ms = (const float4*)&g_M[(size_t)b * DIM * DIM];
        float4* Md = (float4*)sM;
#pragma unroll
        for (int u = 0; u < 8; u++) Md[t + 128 * u] = Ms[t + 128 * u];
    }

    // stage rope(Q) duplicated: 64x64 tile = 1024 float4, 8 per thread
    const size_t gbase = ((size_t)b * SEQ + (size_t)rc * 64) * DIM;
    {
        const float4* Q4 = (const float4*)(Q + gbase);
        const float4* F4 = (const float4*)(FQ + (size_t)rc * 64 * DIM);
#pragma unroll
        for (int u = 0; u < 8; u++) {
            const int f   = t + 128 * u;
            const int row = f >> 4;          // 0..63
            const int d0  = 4 * (f & 15);    // dim start
            const int ii  = row & 3;
            const int rg  = row >> 2;
            const float4 o = rope4(Q4[f], F4[f]);
            *(float2*)&sqd[ii][d0 + 0][2 * PSLOT(rg, d0 + 0)] = make_float2(o.x, o.x);
            *(float2*)&sqd[ii][d0 + 1][2 * PSLOT(rg, d0 + 1)] = make_float2(o.y, o.y);
            *(float2*)&sqd[ii][d0 + 2][2 * PSLOT(rg, d0 + 2)] = make_float2(o.z, o.z);
            *(float2*)&sqd[ii][d0 + 3][2 * PSLOT(rg, d0 + 3)] = make_float2(o.w, o.w);
        }
    }
    __syncthreads();

    const int ti = t & 15;     // row group: rows 4ti..4ti+3
    const int tj = t >> 4;
    const int j0 = 8 * tj;

    ull acc[4][4];
#pragma unroll
    for (int i = 0; i < 4; i++)
#pragma unroll
        for (int u = 0; u < 4; u++) acc[i][u] = 0ULL;

#pragma unroll 16
    for (int d = 0; d < DIM; d++) {
        const int po = 2 * PSLOT(ti, d);
        const ull q0 = *(const ull*)&sqd[0][d][po];
        const ull q1 = *(const ull*)&sqd[1][d][po];
        const ull q2 = *(const ull*)&sqd[2][d][po];
        const ull q3 = *(const ull*)&sqd[3][d][po];
        const ull* mr = (const ull*)&sM[d * DIM + j0];
        const ull m0 = mr[0], m1 = mr[1], m2 = mr[2], m3 = mr[3];
        fma2(acc[0][0], q0, m0); fma2(acc[0][1], q0, m1);
        fma2(acc[0][2], q0, m2); fma2(acc[0][3], q0, m3);
        fma2(acc[1][0], q1, m0); fma2(acc[1][1], q1, m1);
        fma2(acc[1][2], q1, m2); fma2(acc[1][3], q1, m3);
        fma2(acc[2][0], q2, m0); fma2(acc[2][1], q2, m1);
        fma2(acc[2][2], q2, m2); fma2(acc[2][3], q2, m3);
        fma2(acc[3][0], q3, m0); fma2(acc[3][1], q3, m1);
        fma2(acc[3][2], q3, m2); fma2(acc[3][3], q3, m3);
    }

    const float scale = 0.125f;   // 1/sqrt(64)
    float* O = (float*)(OUT + gbase);
    const int i0 = 4 * ti;
#pragma unroll
    for (int i = 0; i < 4; i++) {
#pragma unroll
        for (int w = 0; w < 2; w++) {
            const float2 a  = up2(acc[i][2 * w]);
            const float2 b2 = up2(acc[i][2 * w + 1]);
            *(float4*)&O[(size_t)(i0 + i) * DIM + j0 + 4 * w] =
                make_float4(a.x * scale, a.y * scale, b2.x * scale, b2.y * scale);
        }
    }
}

// ---------------------------------------------------------------------------
extern "C" void kernel_launch(void* const* d_in, const int* in_sizes, int n_in,
                              void* d_out, int out_size)
{
    const float* q  = (const float*)d_in[0];
    const float* k  = (const float*)d_in[1];
    const float* v  = (const float*)d_in[2];
    const float* fq = (const float*)d_in[3];
    const float* fk = (const float*)d_in[4];
    const float* fv = (const float*)d_in[5];
    float* out = (float*)d_out;

    kv_outer_kernel<<<dim3(NCHUNK, BATCH), 128>>>(k, v, fk, fv);
    reduce_kernel<<<(BATCH * DIM * DIM / 4) / 256, 256>>>();
    qm_kernel<<<dim3(SEQ / 64, BATCH), 128>>>(q, fq, out);
}

// round 6
// speedup vs baseline: 1.1701x; 1.1701x over previous
#include <cuda_runtime.h>
#include <cuda_bf16.h>

// B=8, SEQ=4096, DIM=64.
// out = scale * rope(Q) @ (rope(K)^T @ rope(V))   (associativity; no softmax)
// scale = 1/sqrt(64) = 0.125

#define BATCH   8
#define SEQ     4096
#define DIM     64
#define NC1     64            // k1 chunks
#define CHUNK1  (SEQ / NC1)   // 64 rows per k1 CTA (2 halves of 32)
#define NPART   (NC1 * 2)     // 128 partial slots

__device__ float g_partials[NPART * BATCH * DIM * DIM];  // 16 MB
__device__ float g_M[BATCH * DIM * DIM];                 // 128 KB

typedef unsigned long long ull;

__device__ __forceinline__ ull pk2(float x) {
    ull r; asm("mov.b64 %0, {%1,%1};" : "=l"(r) : "f"(x)); return r;
}
__device__ __forceinline__ void fma2(ull& d, ull a, ull b) {
    asm("fma.rn.f32x2 %0, %1, %2, %0;" : "+l"(d) : "l"(a), "l"(b));
}
__device__ __forceinline__ float2 up2(ull v) {
    float2 r; asm("mov.b64 {%0,%1}, %2;" : "=f"(r.x), "=f"(r.y) : "l"(v)); return r;
}
__device__ __forceinline__ float4 rope4(float4 x, float4 f) {
    float4 o;
    o.x = x.x * f.x - x.y * f.y;  o.y = x.x * f.y + x.y * f.x;
    o.z = x.z * f.z - x.w * f.w;  o.w = x.z * f.w + x.w * f.z;
    return o;
}
// interleaved 16B-chunk slot: even chunks -> words 0..31, odd -> 32..63.
// Loading chunks (2j, 2j+1) as LDS at words 4j and 32+4j is conflict-free.
#define SLOT(c) ((((c) >> 1) + 8 * ((c) & 1)) * 4)

// ---------------------------------------------------------------------------
// Kernel 1: partial M = sum_rows rope(k) ⊗ rope(v).  128 threads.
// Half h = t>>6 handles 32 rows; 64 threads/half, thread = 8 rows x 8 cols.
// ---------------------------------------------------------------------------
__global__ __launch_bounds__(128) void kv_outer_kernel(
    const float* __restrict__ K, const float* __restrict__ V,
    const float* __restrict__ FK, const float* __restrict__ FV)
{
    const int b = blockIdx.y;
    const int c = blockIdx.x;
    const int t = threadIdx.x;

    __shared__ float sk[CHUNK1][DIM];    // plain layout, 16 KB
    __shared__ float svI[CHUNK1 * DIM];  // interleaved chunks, 16 KB

    const float4* K4  = (const float4*)(K  + ((size_t)b * SEQ + c * CHUNK1) * DIM);
    const float4* V4  = (const float4*)(V  + ((size_t)b * SEQ + c * CHUNK1) * DIM);
    const float4* FK4 = (const float4*)(FK + (size_t)c * CHUNK1 * DIM);
    const float4* FV4 = (const float4*)(FV + (size_t)c * CHUNK1 * DIM);

    // stage + rope 64x64 tiles: 1024 float4 each, 8 per thread
#pragma unroll
    for (int u = 0; u < 8; u++) {
        const int f  = t + 128 * u;
        const int r  = f >> 4;
        const int c4 = f & 15;
        *(float4*)&sk[r][4 * c4]           = rope4(K4[f], FK4[f]);
        *(float4*)&svI[r * DIM + SLOT(c4)] = rope4(V4[f], FV4[f]);
    }
    __syncthreads();

    const int h  = t >> 6;
    const int lt = t & 63;
    const int ti = lt >> 3;      // rows 8ti..8ti+7
    const int tj = lt & 7;       // cols 8tj..8tj+7
    const int i0 = 8 * ti;
    const int j0 = 8 * tj;

    ull acc[8][4];
#pragma unroll
    for (int i = 0; i < 8; i++)
#pragma unroll
        for (int p = 0; p < 4; p++) acc[i][p] = 0ULL;

    const int rbase = h * 32;
#pragma unroll 4
    for (int r = 0; r < 32; r++) {
        const int row = rbase + r;
        const float4 ka = *(const float4*)&sk[row][i0];
        const float4 kb = *(const float4*)&sk[row][i0 + 4];
        const ull* vA = (const ull*)&svI[row * DIM + 4 * tj];        // cols j0..j0+3
        const ull* vB = (const ull*)&svI[row * DIM + 32 + 4 * tj];   // cols j0+4..j0+7
        const ull v0 = vA[0], v1 = vA[1], v2 = vB[0], v3 = vB[1];
        const ull k0 = pk2(ka.x), k1 = pk2(ka.y), k2 = pk2(ka.z), k3 = pk2(ka.w);
        const ull k4 = pk2(kb.x), k5 = pk2(kb.y), k6 = pk2(kb.z), k7 = pk2(kb.w);
        fma2(acc[0][0], k0, v0); fma2(acc[0][1], k0, v1); fma2(acc[0][2], k0, v2); fma2(acc[0][3], k0, v3);
        fma2(acc[1][0], k1, v0); fma2(acc[1][1], k1, v1); fma2(acc[1][2], k1, v2); fma2(acc[1][3], k1, v3);
        fma2(acc[2][0], k2, v0); fma2(acc[2][1], k2, v1); fma2(acc[2][2], k2, v2); fma2(acc[2][3], k2, v3);
        fma2(acc[3][0], k3, v0); fma2(acc[3][1], k3, v1); fma2(acc[3][2], k3, v2); fma2(acc[3][3], k3, v3);
        fma2(acc[4][0], k4, v0); fma2(acc[4][1], k4, v1); fma2(acc[4][2], k4, v2); fma2(acc[4][3], k4, v3);
        fma2(acc[5][0], k5, v0); fma2(acc[5][1], k5, v1); fma2(acc[5][2], k5, v2); fma2(acc[5][3], k5, v3);
        fma2(acc[6][0], k6, v0); fma2(acc[6][1], k6, v1); fma2(acc[6][2], k6, v2); fma2(acc[6][3], k6, v3);
        fma2(acc[7][0], k7, v0); fma2(acc[7][1], k7, v1); fma2(acc[7][2], k7, v2); fma2(acc[7][3], k7, v3);
    }

    float* P = &g_partials[(((size_t)(2 * c + h)) * BATCH + b) * (DIM * DIM)];
#pragma unroll
    for (int i = 0; i < 8; i++) {
        const float2 a0 = up2(acc[i][0]), a1 = up2(acc[i][1]);
        const float2 a2 = up2(acc[i][2]), a3 = up2(acc[i][3]);
        *(float4*)&P[(i0 + i) * DIM + j0]     = make_float4(a0.x, a0.y, a1.x, a1.y);
        *(float4*)&P[(i0 + i) * DIM + j0 + 4] = make_float4(a2.x, a2.y, a3.x, a3.y);
    }
}

// ---------------------------------------------------------------------------
// Kernel 2: reduce NPART partials -> g_M  (8192 float4 outputs)
// ---------------------------------------------------------------------------
__global__ __launch_bounds__(256) void reduce_kernel()
{
    const int idx = blockIdx.x * 256 + threadIdx.x;
    const float4* P = (const float4*)g_partials;
    float4 s0 = make_float4(0.f, 0.f, 0.f, 0.f);
    float4 s1 = make_float4(0.f, 0.f, 0.f, 0.f);
    float4 s2 = make_float4(0.f, 0.f, 0.f, 0.f);
    float4 s3 = make_float4(0.f, 0.f, 0.f, 0.f);
#pragma unroll 8
    for (int c = 0; c < NPART; c += 4) {
        const float4 a = P[(size_t)(c + 0) * 8192 + idx];
        const float4 b = P[(size_t)(c + 1) * 8192 + idx];
        const float4 d = P[(size_t)(c + 2) * 8192 + idx];
        const float4 e = P[(size_t)(c + 3) * 8192 + idx];
        s0.x += a.x; s0.y += a.y; s0.z += a.z; s0.w += a.w;
        s1.x += b.x; s1.y += b.y; s1.z += b.z; s1.w += b.w;
        s2.x += d.x; s2.y += d.y; s2.z += d.z; s2.w += d.w;
        s3.x += e.x; s3.y += e.y; s3.z += e.z; s3.w += e.w;
    }
    ((float4*)g_M)[idx] = make_float4(s0.x + s1.x + s2.x + s3.x,
                                      s0.y + s1.y + s2.y + s3.y,
                                      s0.z + s1.z + s2.z + s3.z,
                                      s0.w + s1.w + s2.w + s3.w);
}

// ---------------------------------------------------------------------------
// Kernel 3: out = scale * rope(Q) @ M[b].  128 threads, 64 q-rows per CTA.
// q staged transposed (stride 68); M staged interleaved. 4x8 tiles.
// ---------------------------------------------------------------------------
#define QPAD 68

__global__ __launch_bounds__(128) void qm_kernel(
    const float* __restrict__ Q, const float* __restrict__ FQ,
    float* __restrict__ OUT)
{
    const int b  = blockIdx.y;
    const int rc = blockIdx.x;
    const int t  = threadIdx.x;

    __shared__ float sqT[DIM][QPAD];   // 17 KB  [d][row]
    __shared__ float sMI[DIM * DIM];   // 16 KB  interleaved rows

    // stage M[b] interleaved: 1024 float4, 8 per thread  (FIX: was u<4)
    {
        const float4* Ms = (const float4*)&g_M[(size_t)b * DIM * DIM];
#pragma unroll
        for (int u = 0; u < 8; u++) {
            const int f  = t + 128 * u;
            const int d  = f >> 4;
            const int c4 = f & 15;
            *(float4*)&sMI[d * DIM + SLOT(c4)] = Ms[f];
        }
    }

    // stage rope(Q) transposed: 1024 float4, 8 per thread
    const size_t gbase = ((size_t)b * SEQ + (size_t)rc * 64) * DIM;
    {
        const float4* Q4 = (const float4*)(Q + gbase);
        const float4* F4 = (const float4*)(FQ + (size_t)rc * 64 * DIM);
#pragma unroll
        for (int u = 0; u < 8; u++) {
            const int f   = t + 128 * u;
            const int row = f >> 4;          // 0..63
            const int d0  = 4 * (f & 15);
            const float4 o = rope4(Q4[f], F4[f]);
            sqT[d0][row]     = o.x;
            sqT[d0 + 1][row] = o.y;
            sqT[d0 + 2][row] = o.z;
            sqT[d0 + 3][row] = o.w;
        }
    }
    __syncthreads();

    const int ti = t >> 3;    // rows 4ti..4ti+3
    const int tj = t & 7;     // cols 8tj..8tj+7
    const int i0 = 4 * ti;
    const int j0 = 8 * tj;

    ull acc[4][4];
#pragma unroll
    for (int i = 0; i < 4; i++)
#pragma unroll
        for (int p = 0; p < 4; p++) acc[i][p] = 0ULL;

#pragma unroll 8
    for (int d = 0; d < DIM; d++) {
        const float4 qq = *(const float4*)&sqT[d][i0];
        const ull* mA = (const ull*)&sMI[d * DIM + 4 * tj];
        const ull* mB = (const ull*)&sMI[d * DIM + 32 + 4 * tj];
        const ull m0 = mA[0], m1 = mA[1], m2 = mB[0], m3 = mB[1];
        const ull q0 = pk2(qq.x), q1 = pk2(qq.y), q2 = pk2(qq.z), q3 = pk2(qq.w);
        fma2(acc[0][0], q0, m0); fma2(acc[0][1], q0, m1); fma2(acc[0][2], q0, m2); fma2(acc[0][3], q0, m3);
        fma2(acc[1][0], q1, m0); fma2(acc[1][1], q1, m1); fma2(acc[1][2], q1, m2); fma2(acc[1][3], q1, m3);
        fma2(acc[2][0], q2, m0); fma2(acc[2][1], q2, m1); fma2(acc[2][2], q2, m2); fma2(acc[2][3], q2, m3);
        fma2(acc[3][0], q3, m0); fma2(acc[3][1], q3, m1); fma2(acc[3][2], q3, m2); fma2(acc[3][3], q3, m3);
    }

    const float scale = 0.125f;   // 1/sqrt(64)
    float* O = OUT + gbase;
#pragma unroll
    for (int i = 0; i < 4; i++) {
        const float2 a0 = up2(acc[i][0]), a1 = up2(acc[i][1]);
        const float2 a2 = up2(acc[i][2]), a3 = up2(acc[i][3]);
        *(float4*)&O[(size_t)(i0 + i) * DIM + j0] =
            make_float4(a0.x * scale, a0.y * scale, a1.x * scale, a1.y * scale);
        *(float4*)&O[(size_t)(i0 + i) * DIM + j0 + 4] =
            make_float4(a2.x * scale, a2.y * scale, a3.x * scale, a3.y * scale);
    }
}

// ---------------------------------------------------------------------------
extern "C" void kernel_launch(void* const* d_in, const int* in_sizes, int n_in,
                              void* d_out, int out_size)
{
    const float* q  = (const float*)d_in[0];
    const float* k  = (const float*)d_in[1];
    const float* v  = (const float*)d_in[2];
    const float* fq = (const float*)d_in[3];
    const float* fk = (const float*)d_in[4];
    const float* fv = (const float*)d_in[5];
    float* out = (float*)d_out;

    kv_outer_kernel<<<dim3(NC1, BATCH), 128>>>(k, v, fk, fv);
    reduce_kernel<<<(BATCH * DIM * DIM / 4) / 256, 256>>>();
    qm_kernel<<<dim3(SEQ / 64, BATCH), 128>>>(q, fq, out);
}